// round 9
// baseline (speedup 1.0000x reference)
#include <cuda_runtime.h>
#include <cuda_bf16.h>
#include <math.h>
#include <stdint.h>

#define T_STEPS 256
#define BATCH   256
#define OBSD    128
#define HIDD    256
#define HS      512
#define G4      2048
#define ACTD    16
#define TBROWS  (T_STEPS * BATCH)
#define NCTA    128
typedef __nv_bfloat16 BF;

// ---------------- scratch (static device arrays; no cudaMalloc) ----------------
__device__ __align__(16) float g_xgp[(size_t)TBROWS * G4];
__device__ __align__(16) BF    g_fHi[(size_t)TBROWS * HIDD];
__device__ __align__(16) BF    g_fLo[(size_t)TBROWS * HIDD];
__device__ __align__(16) BF    g_hHi[(size_t)TBROWS * HS];
__device__ __align__(16) BF    g_hLo[(size_t)TBROWS * HS];
__device__ __align__(16) BF    g_WhHi[(size_t)G4 * HS];      // [n][k] permuted+transposed
__device__ __align__(16) BF    g_WhLo[(size_t)G4 * HS];
__device__ __align__(16) BF    g_WiHi[(size_t)G4 * HIDD];
__device__ __align__(16) BF    g_WiLo[(size_t)G4 * HIDD];
__device__ __align__(16) float g_bP[G4];
__device__ unsigned g_cnt;

__device__ __forceinline__ float sigmf(float x) { return 1.0f / (1.0f + expf(-x)); }
__device__ __forceinline__ float geluf(float v) {
    float u = 0.7978845608028654f * (v + 0.044715f * v * v * v);
    return 0.5f * v * (1.0f + tanhf(u));
}
__device__ __forceinline__ uint32_t smem_u32(const void* p) {
    uint32_t a;
    asm("{ .reg .u64 t; cvta.to.shared.u64 t, %1; cvt.u32.u64 %0, t; }" : "=r"(a) : "l"(p));
    return a;
}
__device__ __forceinline__ void ldmx4(uint32_t addr, uint32_t* r) {
    asm volatile("ldmatrix.sync.aligned.m8n8.x4.shared.b16 {%0,%1,%2,%3}, [%4];"
        : "=r"(r[0]), "=r"(r[1]), "=r"(r[2]), "=r"(r[3]) : "r"(addr));
}
__device__ __forceinline__ void mma16816(float* d, const uint32_t* a, const uint32_t* b) {
    asm volatile("mma.sync.aligned.m16n8k16.row.col.f32.bf16.bf16.f32 "
        "{%0,%1,%2,%3}, {%4,%5,%6,%7}, {%8,%9}, {%0,%1,%2,%3};"
        : "+f"(d[0]), "+f"(d[1]), "+f"(d[2]), "+f"(d[3])
        : "r"(a[0]), "r"(a[1]), "r"(a[2]), "r"(a[3]), "r"(b[0]), "r"(b[1]));
}
#define CP_COMMIT() asm volatile("cp.async.commit_group;" ::: "memory")
#define CP_WAIT0()  asm volatile("cp.async.wait_group 0;" ::: "memory")

// A stage stride: 136 elems (272B, ≡16 mod 128 -> conflict-free ldmatrix)
#define AST 136
#define CHUNK_BYTES 17408          // 64 x 136 bf16
// ---- scan SMEM map (bytes) ----
#define S_W_HI  0
#define S_W_LO  66560
#define S_BUF0  133120             // [hi 17408][lo 17408]
#define S_BUF1  167936
#define S_PART  133120             // alias over both A buffers (69632 B)
#define S_CS    202752             // cell state 64x16 fp32
#define S_DYN   206848
#define WST_S   520
// ---- x_gates SMEM map ----
#define X_W_HI  0
#define X_W_LO  33792
#define X_BUF0  67584
#define X_BUF1  102400
#define X_PART  67584
#define X_DYN   137216
#define WST_X   264

// cp.async one K=128 chunk (64 rows) of A hi/lo into stage buffer
__device__ __forceinline__ void stage_cp(uint32_t dHi, uint32_t dLo,
                                         const BF* sHi, const BF* sLo,
                                         int ld, int tid) {
#pragma unroll
    for (int p = 0; p < 4; p++) {
        int j = tid + p * 256;
        int r = j >> 4, cb = j & 15;
        const BF* sh = sHi + (size_t)r * ld + cb * 8;
        const BF* sl = sLo + (size_t)r * ld + cb * 8;
        uint32_t dh = dHi + r * 272 + cb * 16;
        uint32_t dl = dLo + r * 272 + cb * 16;
        asm volatile("cp.async.cg.shared.global [%0], [%1], 16;\n\t"
                     "cp.async.cg.shared.global [%2], [%3], 16;"
                     :: "r"(dh), "l"(sh), "r"(dl), "l"(sl));
    }
}

// Warp (ng, kg): m64 x n32 tile, 2 ksteps of this chunk (kg*2, kg*2+1), 3 split passes.
__device__ __forceinline__ void mma_2ks(uint32_t aHi, uint32_t aLo,
                                        uint32_t wHi, uint32_t wLo, int wst,
                                        int kg, int gk0, int ng, int lane,
                                        float acc[4][4][4]) {
#pragma unroll
    for (int s = 0; s < 2; s++) {
        int lks = kg * 2 + s;
        int gks = gk0 + lks;
        uint32_t bh[2][4], bl[2][4];
#pragma unroll
        for (int h = 0; h < 2; h++) {
            int nrow = ng * 32 + h * 16 + (lane & 7) + ((lane >> 4) << 3);
            int kcol = gks * 16 + ((lane >> 3) & 1) * 8;
            ldmx4(wHi + (nrow * wst + kcol) * 2, bh[h]);
            ldmx4(wLo + (nrow * wst + kcol) * 2, bl[h]);
        }
#pragma unroll
        for (int mt = 0; mt < 4; mt++) {
            uint32_t ah[4], al[4];
            int row = mt * 16 + (lane & 15);
            int col = lks * 16 + ((lane >> 4) << 3);
            ldmx4(aHi + (row * AST + col) * 2, ah);
            ldmx4(aLo + (row * AST + col) * 2, al);
#pragma unroll
            for (int h = 0; h < 2; h++)
#pragma unroll
                for (int q = 0; q < 2; q++) {
                    int nt = h * 2 + q;
                    mma16816(acc[mt][nt], ah, &bh[h][q * 2]);
                    mma16816(acc[mt][nt], ah, &bl[h][q * 2]);
                    mma16816(acc[mt][nt], al, &bh[h][q * 2]);
                }
        }
    }
}

// STS k-split partials: part[kg][row 64][col 64], stride 68 floats
__device__ __forceinline__ void sts_part(float* part, float acc[4][4][4],
                                         int kg, int ng, int lane) {
#pragma unroll
    for (int mt = 0; mt < 4; mt++)
#pragma unroll
        for (int nt = 0; nt < 4; nt++) {
            int row0 = mt * 16 + (lane >> 2);
            int col = ng * 32 + nt * 8 + (lane & 3) * 2;
            *(float2*)&part[(kg * 64 + row0) * 68 + col] = *(float2*)&acc[mt][nt][0];
            *(float2*)&part[(kg * 64 + row0 + 8) * 68 + col] = *(float2*)&acc[mt][nt][2];
        }
}

// ---------------- prep ----------------
__global__ void prep_kernel(const float* __restrict__ Wi, const float* __restrict__ Wh,
                            const float* __restrict__ bl) {
    int stride = gridDim.x * blockDim.x;
    int idx = blockIdx.x * blockDim.x + threadIdx.x;
    for (int i = idx; i < G4 * HS; i += stride) {
        int n = i >> 9, k = i & (HS - 1);
        float v = Wh[(size_t)k * G4 + (n & 3) * HS + (n >> 2)];
        BF h = __float2bfloat16(v);
        g_WhHi[i] = h; g_WhLo[i] = __float2bfloat16(v - __bfloat162float(h));
    }
    for (int i = idx; i < G4 * HIDD; i += stride) {
        int n = i >> 8, k = i & (HIDD - 1);
        float v = Wi[(size_t)k * G4 + (n & 3) * HS + (n >> 2)];
        BF h = __float2bfloat16(v);
        g_WiHi[i] = h; g_WiLo[i] = __float2bfloat16(v - __bfloat162float(h));
    }
    for (int i = idx; i < G4; i += stride)
        g_bP[i] = bl[(i & 3) * HS + (i >> 2)];
    if (idx == 0) g_cnt = 0;
}

// ---------------- encoder ----------------
__global__ void __launch_bounds__(256) enc_kernel(const float* __restrict__ A,
                                                  const float* __restrict__ B,
                                                  const float* __restrict__ bias) {
    __shared__ float As[64 * 68];
    __shared__ float Bs[64 * 64];
    int nb = blockIdx.x, mb = blockIdx.y, tid = threadIdx.x;
    int tn = tid & 15, tm = tid >> 4;
    float acc[4][4];
#pragma unroll
    for (int i = 0; i < 4; i++)
#pragma unroll
        for (int j = 0; j < 4; j++) acc[i][j] = 0.f;
    for (int kc = 0; kc < 2; kc++) {
        __syncthreads();
#pragma unroll
        for (int p = 0; p < 4; p++) {
            int idx = p * 256 + tid, r = idx >> 4, c4 = (idx & 15) << 2;
            *(float4*)&As[r * 68 + c4] = *(const float4*)&A[(size_t)(mb * 64 + r) * OBSD + kc * 64 + c4];
            *(float4*)&Bs[r * 64 + c4] = *(const float4*)&B[(size_t)(kc * 64 + r) * HIDD + nb * 64 + c4];
        }
        __syncthreads();
#pragma unroll 8
        for (int kk = 0; kk < 64; kk++) {
            float4 w = *(const float4*)&Bs[kk * 64 + tn * 4];
#pragma unroll
            for (int i = 0; i < 4; i++) {
                float a = As[(tm * 4 + i) * 68 + kk];
                acc[i][0] += a * w.x; acc[i][1] += a * w.y;
                acc[i][2] += a * w.z; acc[i][3] += a * w.w;
            }
        }
    }
    int n0 = nb * 64 + tn * 4;
    float4 bb = *(const float4*)&bias[n0];
#pragma unroll
    for (int i = 0; i < 4; i++) {
        int row = mb * 64 + tm * 4 + i;
        float v[4] = { geluf(acc[i][0] + bb.x), geluf(acc[i][1] + bb.y),
                       geluf(acc[i][2] + bb.z), geluf(acc[i][3] + bb.w) };
        __align__(8) BF hb[4], lb[4];
#pragma unroll
        for (int q = 0; q < 4; q++) {
            hb[q] = __float2bfloat16(v[q]);
            lb[q] = __float2bfloat16(v[q] - __bfloat162float(hb[q]));
        }
        *(int2*)(g_fHi + (size_t)row * HIDD + n0) = *(int2*)hb;
        *(int2*)(g_fLo + (size_t)row * HIDD + n0) = *(int2*)lb;
    }
}

// ---------------- x_gates (bf16-split HMMA, n-split x k-split warps) ----------------
__global__ void __launch_bounds__(256) xg_mma_kernel() {
    extern __shared__ char sm[];
    uint32_t sb = smem_u32(sm);
    int tid = threadIdx.x, lane = tid & 31, wid = tid >> 5;
    int nb = blockIdx.x, my = blockIdx.y;
    int ng = wid & 1, kg = wid >> 1;

    // resident W slice [64][256] hi/lo
    {
        BF* Whi = (BF*)(sm + X_W_HI);
        BF* Wlo = (BF*)(sm + X_W_LO);
        const BF* sh = g_WiHi + (size_t)(nb * 64) * HIDD;
        const BF* sl = g_WiLo + (size_t)(nb * 64) * HIDD;
        for (int i = tid; i < 2048; i += 256) {
            int r = i >> 5, c8 = (i & 31) * 8;
            *(int4*)&Whi[r * WST_X + c8] = *(const int4*)&sh[(size_t)r * HIDD + c8];
            *(int4*)&Wlo[r * WST_X + c8] = *(const int4*)&sl[(size_t)r * HIDD + c8];
        }
    }
    float acc[4][4][4];
#pragma unroll
    for (int a = 0; a < 4; a++)
#pragma unroll
        for (int b = 0; b < 4; b++)
#pragma unroll
            for (int e = 0; e < 4; e++) acc[a][b][e] = 0.f;

    const BF* Ah = g_fHi + (size_t)(my * 64) * HIDD;
    const BF* Al = g_fLo + (size_t)(my * 64) * HIDD;
    const uint32_t bufs[2] = { sb + X_BUF0, sb + X_BUF1 };

    stage_cp(bufs[0], bufs[0] + CHUNK_BYTES, Ah, Al, HIDD, tid);
    CP_COMMIT();
#pragma unroll
    for (int ch = 0; ch < 2; ch++) {
        CP_WAIT0();
        __syncthreads();
        if (ch < 1) {
            stage_cp(bufs[1], bufs[1] + CHUNK_BYTES, Ah + 128, Al + 128, HIDD, tid);
            CP_COMMIT();
        }
        mma_2ks(bufs[ch], bufs[ch] + CHUNK_BYTES, sb + X_W_HI, sb + X_W_LO,
                WST_X, kg, ch * 8, ng, lane, acc);
    }
    __syncthreads();
    float* part = (float*)(sm + X_PART);
    sts_part(part, acc, kg, ng, lane);
    __syncthreads();

    int erow = tid >> 2, eu4 = tid & 3;
    int col0 = nb * 64 + eu4 * 16;
    float* op = g_xgp + ((size_t)my * 64 + erow) * G4 + col0;
#pragma unroll
    for (int j = 0; j < 16; j += 4) {
        float4 v = *(const float4*)&part[(0 * 64 + erow) * 68 + eu4 * 16 + j];
#pragma unroll
        for (int k = 1; k < 4; k++) {
            float4 p = *(const float4*)&part[(k * 64 + erow) * 68 + eu4 * 16 + j];
            v.x += p.x; v.y += p.y; v.z += p.z; v.w += p.w;
        }
        float4 bb = *(const float4*)&g_bP[col0 + j];
        v.x += bb.x; v.y += bb.y; v.z += bb.z; v.w += bb.w;
        *(float4*)(op + j) = v;
    }
}

// ---------------- persistent HMMA LSTM scan ----------------
// 128 CTAs = 4 mb(64 batch) x 32 nb(64 gate cols). 8 warps = 2 n-groups x 4 k-groups.
__global__ void __launch_bounds__(256) scan_mma_kernel() {
    extern __shared__ char sm[];
    uint32_t sb = smem_u32(sm);
    float* cS = (float*)(sm + S_CS);
    float* part = (float*)(sm + S_PART);
    int tid = threadIdx.x, lane = tid & 31, wid = tid >> 5;
    int mb = blockIdx.x >> 5, nb = blockIdx.x & 31;
    int ng = wid & 1, kg = wid >> 1;

    // resident Wh slice [64][512] hi/lo
    {
        BF* Whi = (BF*)(sm + S_W_HI);
        BF* Wlo = (BF*)(sm + S_W_LO);
        const BF* sh = g_WhHi + (size_t)(nb * 64) * HS;
        const BF* sl = g_WhLo + (size_t)(nb * 64) * HS;
        for (int i = tid; i < 4096; i += 256) {
            int r = i >> 6, c8 = (i & 63) * 8;
            *(int4*)&Whi[r * WST_S + c8] = *(const int4*)&sh[(size_t)r * HS + c8];
            *(int4*)&Wlo[r * WST_S + c8] = *(const int4*)&sl[(size_t)r * HS + c8];
        }
    }
    for (int i = tid; i < 64 * 16; i += 256) cS[i] = 0.f;
    __syncthreads();

    int erow = tid >> 2, eu4 = tid & 3;
    const uint32_t bufs[2] = { sb + S_BUF0, sb + S_BUF1 };

#pragma unroll 1
    for (int t = 0; t < T_STEPS; t++) {
        // prefetch this thread's gate inputs
        const float* xgp = g_xgp + ((size_t)t * BATCH + mb * 64 + erow) * G4 + nb * 64 + eu4 * 16;
        float xr[16];
        *(float4*)&xr[0]  = *(const float4*)(xgp + 0);
        *(float4*)&xr[4]  = *(const float4*)(xgp + 4);
        *(float4*)&xr[8]  = *(const float4*)(xgp + 8);
        *(float4*)&xr[12] = *(const float4*)(xgp + 12);

        if (t > 0) {
            float acc[4][4][4];
#pragma unroll
            for (int a = 0; a < 4; a++)
#pragma unroll
                for (int b = 0; b < 4; b++)
#pragma unroll
                    for (int e = 0; e < 4; e++) acc[a][b][e] = 0.f;

            const BF* Ah = g_hHi + ((size_t)(t - 1) * BATCH + mb * 64) * HS;
            const BF* Al = g_hLo + ((size_t)(t - 1) * BATCH + mb * 64) * HS;

            stage_cp(bufs[0], bufs[0] + CHUNK_BYTES, Ah, Al, HS, tid);
            CP_COMMIT();
#pragma unroll 1
            for (int ch = 0; ch < 4; ch++) {
                CP_WAIT0();
                __syncthreads();
                if (ch < 3) {
                    uint32_t nbuf = bufs[(ch + 1) & 1];
                    stage_cp(nbuf, nbuf + CHUNK_BYTES,
                             Ah + (ch + 1) * 128, Al + (ch + 1) * 128, HS, tid);
                    CP_COMMIT();
                }
                mma_2ks(bufs[ch & 1], bufs[ch & 1] + CHUNK_BYTES,
                        sb + S_W_HI, sb + S_W_LO, WST_S, kg, ch * 8, ng, lane, acc);
            }
            __syncthreads();              // A buffers dead -> safe to alias part
            sts_part(part, acc, kg, ng, lane);
        }
        __syncthreads();

        // epilogue: 4 units per thread, c in SMEM (thread-exclusive slot)
        float g[16];
#pragma unroll
        for (int j = 0; j < 16; j += 4) *(float4*)&g[j] = make_float4(0.f, 0.f, 0.f, 0.f);
        if (t > 0) {
#pragma unroll
            for (int k = 0; k < 4; k++)
#pragma unroll
                for (int j = 0; j < 16; j += 4) {
                    float4 p = *(const float4*)&part[(k * 64 + erow) * 68 + eu4 * 16 + j];
                    g[j] += p.x; g[j + 1] += p.y; g[j + 2] += p.z; g[j + 3] += p.w;
                }
        }
        float* cp = &cS[erow * 16 + eu4 * 4];
        __align__(8) BF hb[4], lb[4];
#pragma unroll
        for (int q = 0; q < 4; q++) {
            float zi = g[q * 4 + 0] + xr[q * 4 + 0];
            float zf = g[q * 4 + 1] + xr[q * 4 + 1];
            float zg = g[q * 4 + 2] + xr[q * 4 + 2];
            float zo = g[q * 4 + 3] + xr[q * 4 + 3];
            float cn = sigmf(zf) * cp[q] + sigmf(zi) * tanhf(zg);
            cp[q] = cn;
            float hv = sigmf(zo) * tanhf(cn);
            BF hh = __float2bfloat16(hv);
            hb[q] = hh;
            lb[q] = __float2bfloat16(hv - __bfloat162float(hh));
        }
        size_t ho = ((size_t)t * BATCH + mb * 64 + erow) * HS + nb * 16 + eu4 * 4;
        *(int2*)&g_hHi[ho] = *(int2*)hb;
        *(int2*)&g_hLo[ho] = *(int2*)lb;

        // grid barrier
        __syncthreads();
        if (tid == 0) {
            __threadfence();
            atomicAdd(&g_cnt, 1u);
            unsigned target = (unsigned)(t + 1) * NCTA, v;
            do {
                asm volatile("ld.acquire.gpu.u32 %0, [%1];" : "=r"(v) : "l"(&g_cnt) : "memory");
            } while (v < target);
        }
        __syncthreads();
    }
}

// ---------------- heads ----------------
__global__ void __launch_bounds__(256) heads_kernel(
    const float* __restrict__ Wmu, const float* __restrict__ bmu,
    const float* __restrict__ lstd, const float* __restrict__ Wv,
    const float* __restrict__ bv, float* __restrict__ out) {
    __shared__ float Wt[17 * HS];
    __shared__ float sig_s[16], bias_s[17];
    int tid = threadIdx.x;
    for (int i = tid; i < HS * ACTD; i += 256) {
        int k = i >> 4, a = i & 15;
        Wt[a * HS + k] = Wmu[(size_t)k * ACTD + a];
    }
    for (int i = tid; i < HS; i += 256) Wt[16 * HS + i] = Wv[i];
    if (tid < 16) { sig_s[tid] = expf(lstd[tid]); bias_s[tid] = bmu[tid]; }
    if (tid == 16) bias_s[16] = bv[0];
    __syncthreads();

    int warp = tid >> 5, lane = tid & 31;
    int step = gridDim.x * 8;
    for (int row = blockIdx.x * 8 + warp; row < TBROWS; row += step) {
        const BF* hh = g_hHi + (size_t)row * HS;
        const BF* hl = g_hLo + (size_t)row * HS;
        float acc[17];
#pragma unroll
        for (int a = 0; a < 17; a++) acc[a] = 0.f;
#pragma unroll 4
        for (int q = 0; q < 16; q++) {
            int idx = q * 32 + lane;
            float hv = __bfloat162float(hh[idx]) + __bfloat162float(hl[idx]);
#pragma unroll
            for (int a = 0; a < 17; a++) acc[a] += hv * Wt[a * HS + idx];
        }
#pragma unroll
        for (int a = 0; a < 17; a++)
#pragma unroll
            for (int off = 16; off > 0; off >>= 1)
                acc[a] += __shfl_xor_sync(0xffffffffu, acc[a], off);
        if (lane < 16) {
            out[(size_t)row * ACTD + lane] = acc[lane] + bias_s[lane];
            out[(size_t)TBROWS * ACTD + (size_t)row * ACTD + lane] = sig_s[lane];
        }
        if (lane == 0)
            out[(size_t)TBROWS * ACTD * 2 + row] = acc[16] + bias_s[16];
    }
}

// ---------------- launch ----------------
extern "C" void kernel_launch(void* const* d_in, const int* in_sizes, int n_in,
                              void* d_out, int out_size) {
    const float* x     = (const float*)d_in[0];
    const float* W_enc = (const float*)d_in[1];
    const float* b_enc = (const float*)d_in[2];
    const float* Wi    = (const float*)d_in[3];
    const float* Wh    = (const float*)d_in[4];
    const float* b_l   = (const float*)d_in[5];
    const float* W_mu  = (const float*)d_in[6];
    const float* b_mu  = (const float*)d_in[7];
    const float* lstd  = (const float*)d_in[8];
    const float* W_v   = (const float*)d_in[9];
    const float* b_v   = (const float*)d_in[10];
    float* out = (float*)d_out;

    cudaFuncSetAttribute(xg_mma_kernel,   cudaFuncAttributeMaxDynamicSharedMemorySize, X_DYN);
    cudaFuncSetAttribute(scan_mma_kernel, cudaFuncAttributeMaxDynamicSharedMemorySize, S_DYN);

    prep_kernel<<<1024, 256>>>(Wi, Wh, b_l);
    enc_kernel<<<dim3(HIDD / 64, TBROWS / 64), 256>>>(x, W_enc, b_enc);
    xg_mma_kernel<<<dim3(32, TBROWS / 64), 256, X_DYN>>>();
    scan_mma_kernel<<<NCTA, 256, S_DYN>>>();
    heads_kernel<<<1024, 256>>>(W_mu, b_mu, lstd, W_v, b_v, out);
}